// round 5
// baseline (speedup 1.0000x reference)
#include <cuda_runtime.h>
#include <cuda_bf16.h>

#define FULLMASK 0xffffffffu
#define BB 2048
#define TT 4096

// ---- device scratch (allocation-free) ----
__device__ float g_s0part[8][64];    // feature col partial sum/sumsq per block
__device__ float g_a1part[16][16];   // h1 partial stats per block
__device__ float g_a2part[16][16];   // h2 partial stats per block
__device__ float g_h1[BB * 8];
__device__ float g_h2[BB * 8];
__device__ float g_params[BB * 8];   // f_inf, df, kf, G, z0, lw, R, pad

// ============ K1: bn0 column stats over features [2048,32] ============
// grid 8 x 256: block handles 256 rows; warp handles 32 rows.
__global__ __launch_bounds__(256) void k1_stats0(const float* __restrict__ features) {
    __shared__ float red[8][64];
    int t = threadIdx.x, lane = t & 31, warp = t >> 5;
    int rbase = blockIdx.x * 256 + warp * 32 + (lane >> 3);
    int cg = (lane & 7) * 4;
    float s0=0,s1=0,s2=0,s3=0,q0=0,q1=0,q2=0,q3=0;
    #pragma unroll
    for (int i = 0; i < 8; i++) {
        float4 v = *(const float4*)(features + (size_t)(rbase + i * 4) * 32 + cg);
        s0 += v.x; s1 += v.y; s2 += v.z; s3 += v.w;
        q0 = fmaf(v.x, v.x, q0); q1 = fmaf(v.y, v.y, q1);
        q2 = fmaf(v.z, v.z, q2); q3 = fmaf(v.w, v.w, q3);
    }
    #pragma unroll
    for (int d = 8; d <= 16; d <<= 1) {
        s0 += __shfl_xor_sync(FULLMASK, s0, d); s1 += __shfl_xor_sync(FULLMASK, s1, d);
        s2 += __shfl_xor_sync(FULLMASK, s2, d); s3 += __shfl_xor_sync(FULLMASK, s3, d);
        q0 += __shfl_xor_sync(FULLMASK, q0, d); q1 += __shfl_xor_sync(FULLMASK, q1, d);
        q2 += __shfl_xor_sync(FULLMASK, q2, d); q3 += __shfl_xor_sync(FULLMASK, q3, d);
    }
    if (lane < 8) {
        red[warp][cg + 0] = s0; red[warp][cg + 1] = s1;
        red[warp][cg + 2] = s2; red[warp][cg + 3] = s3;
        red[warp][32 + cg + 0] = q0; red[warp][32 + cg + 1] = q1;
        red[warp][32 + cg + 2] = q2; red[warp][32 + cg + 3] = q3;
    }
    __syncthreads();
    if (t < 64) {
        float a = 0.f;
        #pragma unroll
        for (int w = 0; w < 8; w++) a += red[w][t];
        g_s0part[blockIdx.x][t] = a;
    }
}

// ============ K2: finalize bn0, h1 = bn0(features)@W1^T + b1, bn1 partials ============
__global__ __launch_bounds__(128) void k2_h1(const float* __restrict__ features,
                                             const float* __restrict__ bn0_g,
                                             const float* __restrict__ bn0_b,
                                             const float* __restrict__ W1,
                                             const float* __restrict__ b1) {
    __shared__ float sc0[32], sh0[32], sW[256], sb[8], wpart[4][16];
    int t = threadIdx.x;
    if (t < 32) {
        float ss = 0.f, qq = 0.f;
        #pragma unroll
        for (int k = 0; k < 8; k++) { ss += g_s0part[k][t]; qq += g_s0part[k][32 + t]; }
        float mean = ss * (1.f / 2048.f);
        float var = qq * (1.f / 2048.f) - mean * mean;
        float sc = bn0_g[t] * rsqrtf(var + 1e-5f);
        sc0[t] = sc; sh0[t] = bn0_b[t] - mean * sc;
    }
    sW[t] = W1[t]; sW[t + 128] = W1[t + 128];
    if (t < 8) sb[t] = b1[t];
    __syncthreads();

    int row = blockIdx.x * 128 + t;
    const float4* fp = (const float4*)(features + (size_t)row * 32);
    float x[32];
    #pragma unroll
    for (int i = 0; i < 8; i++) {
        float4 v = fp[i];
        x[4*i] = v.x; x[4*i+1] = v.y; x[4*i+2] = v.z; x[4*i+3] = v.w;
    }
    #pragma unroll
    for (int c = 0; c < 32; c++) x[c] = fmaf(x[c], sc0[c], sh0[c]);
    float h[8];
    #pragma unroll
    for (int j = 0; j < 8; j++) {
        float acc = sb[j];
        #pragma unroll
        for (int c = 0; c < 32; c++) acc = fmaf(sW[j * 32 + c], x[c], acc);
        h[j] = acc;
    }
    float4* hp = (float4*)(g_h1 + row * 8);
    hp[0] = make_float4(h[0], h[1], h[2], h[3]);
    hp[1] = make_float4(h[4], h[5], h[6], h[7]);

    float sv[16];
    #pragma unroll
    for (int j = 0; j < 8; j++) { sv[j] = h[j]; sv[8 + j] = h[j] * h[j]; }
    #pragma unroll
    for (int d = 16; d; d >>= 1) {
        #pragma unroll
        for (int j = 0; j < 16; j++) sv[j] += __shfl_xor_sync(FULLMASK, sv[j], d);
    }
    int warp = t >> 5, lane = t & 31;
    if (lane == 0) {
        #pragma unroll
        for (int j = 0; j < 16; j++) wpart[warp][j] = sv[j];
    }
    __syncthreads();
    if (t < 16)
        g_a1part[blockIdx.x][t] = wpart[0][t] + wpart[1][t] + wpart[2][t] + wpart[3][t];
}

// ============ K3: finalize bn1, h2 = relu(bn1(h1))@W2^T + b2, bn2 partials ============
__global__ __launch_bounds__(128) void k3_h2(const float* __restrict__ bn1_g,
                                             const float* __restrict__ bn1_b,
                                             const float* __restrict__ W2,
                                             const float* __restrict__ b2) {
    __shared__ float sc1[8], sh1[8], sW[64], sb[8], wpart[4][16];
    int t = threadIdx.x;
    if (t < 8) {
        float ss = 0.f, qq = 0.f;
        #pragma unroll
        for (int k = 0; k < 16; k++) { ss += g_a1part[k][t]; qq += g_a1part[k][8 + t]; }
        float mean = ss * (1.f / 2048.f);
        float var = qq * (1.f / 2048.f) - mean * mean;
        float sc = bn1_g[t] * rsqrtf(var + 1e-5f);
        sc1[t] = sc; sh1[t] = bn1_b[t] - mean * sc;
    }
    if (t < 64) sW[t] = W2[t];
    if (t < 8) sb[t] = b2[t];
    __syncthreads();

    int row = blockIdx.x * 128 + t;
    const float4* hp = (const float4*)(g_h1 + row * 8);
    float4 v0 = hp[0], v1 = hp[1];
    float z[8] = {v0.x, v0.y, v0.z, v0.w, v1.x, v1.y, v1.z, v1.w};
    #pragma unroll
    for (int j = 0; j < 8; j++) z[j] = fmaxf(fmaf(z[j], sc1[j], sh1[j]), 0.f);
    float h[8];
    #pragma unroll
    for (int k = 0; k < 8; k++) {
        float acc = sb[k];
        #pragma unroll
        for (int j = 0; j < 8; j++) acc = fmaf(sW[k * 8 + j], z[j], acc);
        h[k] = acc;
    }
    float4* op = (float4*)(g_h2 + row * 8);
    op[0] = make_float4(h[0], h[1], h[2], h[3]);
    op[1] = make_float4(h[4], h[5], h[6], h[7]);

    float sv[16];
    #pragma unroll
    for (int j = 0; j < 8; j++) { sv[j] = h[j]; sv[8 + j] = h[j] * h[j]; }
    #pragma unroll
    for (int d = 16; d; d >>= 1) {
        #pragma unroll
        for (int j = 0; j < 16; j++) sv[j] += __shfl_xor_sync(FULLMASK, sv[j], d);
    }
    int warp = t >> 5, lane = t & 31;
    if (lane == 0) {
        #pragma unroll
        for (int j = 0; j < 16; j++) wpart[warp][j] = sv[j];
    }
    __syncthreads();
    if (t < 16)
        g_a2part[blockIdx.x][t] = wpart[0][t] + wpart[1][t] + wpart[2][t] + wpart[3][t];
}

// ============ K4: finalize bn2, corr = relu(bn2(h2))@W3^T + b3 -> scan params ============
__global__ __launch_bounds__(128) void k4_params(const float* __restrict__ bn2_g,
                                                 const float* __restrict__ bn2_b,
                                                 const float* __restrict__ W3,
                                                 const float* __restrict__ b3,
                                                 const float* __restrict__ pn) {
    __shared__ float sc2[8], sh2[8], sW[48], sb[6], spn[6];
    int t = threadIdx.x;
    if (t < 8) {
        float ss = 0.f, qq = 0.f;
        #pragma unroll
        for (int k = 0; k < 16; k++) { ss += g_a2part[k][t]; qq += g_a2part[k][8 + t]; }
        float mean = ss * (1.f / 2048.f);
        float var = qq * (1.f / 2048.f) - mean * mean;
        float sc = bn2_g[t] * rsqrtf(var + 1e-5f);
        sc2[t] = sc; sh2[t] = bn2_b[t] - mean * sc;
    }
    if (t < 48) sW[t] = W3[t];
    if (t < 6) { sb[t] = b3[t]; spn[t] = pn[t]; }
    __syncthreads();

    int row = blockIdx.x * 128 + t;
    const float4* hp = (const float4*)(g_h2 + row * 8);
    float4 v0 = hp[0], v1 = hp[1];
    float z[8] = {v0.x, v0.y, v0.z, v0.w, v1.x, v1.y, v1.z, v1.w};
    #pragma unroll
    for (int j = 0; j < 8; j++) z[j] = fmaxf(fmaf(z[j], sc2[j], sh2[j]), 0.f);
    float sg[6];
    #pragma unroll
    for (int j = 0; j < 6; j++) {
        float acc = sb[j] + spn[j];
        #pragma unroll
        for (int k = 0; k < 8; k++) acc = fmaf(sW[j * 8 + k], z[k], acc);
        sg[j] = 1.f / (1.f + expf(-acc));
    }
    float f_start = fmaf(4.5f, sg[0], 0.5f);
    float f_inf   = fmaf(0.49f, sg[1], 0.01f);
    float f_decay = 2.f * sg[2];
    float f_T     = 2.f * sg[3];
    float w_off   = sg[4];
    float w_T     = fmaf(0.49f, sg[5], 0.01f);

    float df  = f_start - f_inf;
    float lnD = fmaf(-2.30258509f, f_decay, -0.35667494f);  // ln(0.7*0.1^fd)
    float H   = 10.f * expf(-2.30258509f * f_T);            // 10*0.1^fT
    float kf  = lnD / (4096.f * H);
    float G   = expf(kf);
    float z0  = w_off / w_T;
    float lw  = -1.f / (4096.f * w_T);
    float R   = expf(lw);

    float4* op = (float4*)(g_params + row * 8);
    op[0] = make_float4(f_inf, df, kf, G);
    op[1] = make_float4(z0, lw, R, 0.f);
}

// ============ K5: affine-chunked IIR scan + weighted average ============
// One warp per row; lane l scans steps [128l, 128l+128) in closed affine form
// (y1,y2 state; transform [[p,0],[r,p]] + offset (q1,q2)); weighted-output
// accumulators (a1,a2,bt,ws) are affine in the chunk's entry state. 5-round
// shfl_up exclusive scan composes chunks, then a butterfly reduce finishes.
__global__ __launch_bounds__(256) void k5_scan(const float* __restrict__ X,
                                               const float* __restrict__ Fp,
                                               float* __restrict__ out) {
    int warp = threadIdx.x >> 5, lane = threadIdx.x & 31;
    int row = blockIdx.x * 8 + warp;
    const float cc = 0.16228221f * __ldg(Fp);   // sqrt(2^(1/3)-1)*F/pi

    const float4 c0 = *(const float4*)(g_params + row * 8);
    const float4 c1 = *(const float4*)(g_params + row * 8 + 4);
    const float f_inf = c0.x, df = c0.y, kf = c0.z, G = c0.w;
    const float z0 = c1.x, lw = c1.y, R = c1.z;

    const float* xrow = X + (size_t)row * TT;
    const int t0 = lane << 7;
    float g = __expf(kf * (float)t0);
    float e = __expf(fmaf(lw, (float)t0, z0));  // may be inf -> w=0 (correct)
    float xp = xrow[t0 ? t0 - 1 : 0];

    float p = 1.f, r = 0.f, q1 = 0.f, q2 = 0.f;
    float a1 = 0.f, a2 = 0.f, bt = 0.f, ws = 0.f;

    const float4* xv = (const float4*)(xrow + t0);
    float4 v = xv[0];
    const float y0 = __shfl_sync(FULLMASK, v.x, 0);

#define STEP(xval) do {                               \
    float w_ = __fdividef(1.f, 1.f + e);              \
    float f_ = fmaf(df, g, f_inf);                    \
    float ap = __fdividef(cc - f_, cc + f_);          \
    g *= G; e *= R;                                   \
    float b_ = fmaf(-0.5f, ap, 0.5f);                 \
    float m_ = fmaf(b_, ap, b_);                      \
    float xx = (xval) + xp;                           \
    float u1 = b_ * xx;                               \
    float u2 = b_ * u1;                               \
    float pm = m_ * p;                                \
    float t2 = fmaf(m_, q1, u2);                      \
    p = ap * p;                                       \
    r = fmaf(ap, r, pm);                              \
    q1 = fmaf(ap, q1, u1);                            \
    q2 = fmaf(ap, q2, t2);                            \
    a1 = fmaf(w_, r, a1);                             \
    a2 = fmaf(w_, p, a2);                             \
    bt = fmaf(w_, q2, bt);                            \
    ws += w_;                                         \
    xp = (xval);                                      \
  } while (0)

    if (lane == 0) {
        // t = 0: y2_0 = y0 = y2_in, identity transform -> a2 += w0, ws += w0
        float w0 = __fdividef(1.f, 1.f + e);
        a2 = w0; ws = w0;
        g *= G; e *= R;
        // xp stays X[0] for the t=1 step
    } else {
        STEP(v.x);
    }
    STEP(v.y); STEP(v.z); STEP(v.w);
    #pragma unroll 2
    for (int i = 1; i < 32; i++) {
        v = xv[i];
        STEP(v.x); STEP(v.y); STEP(v.z); STEP(v.w);
    }
#undef STEP

    // inclusive scan: compose self ∘ (prefix from lower lanes)
    #pragma unroll
    for (int d = 1; d < 32; d <<= 1) {
        float pL  = __shfl_up_sync(FULLMASK, p,  d);
        float rL  = __shfl_up_sync(FULLMASK, r,  d);
        float q1L = __shfl_up_sync(FULLMASK, q1, d);
        float q2L = __shfl_up_sync(FULLMASK, q2, d);
        if (lane >= d) {
            float pn  = p * pL;
            float rn  = fmaf(r, pL, p * rL);
            float q1n = fmaf(p, q1L, q1);
            float q2n = fmaf(r, q1L, fmaf(p, q2L, q2));
            p = pn; r = rn; q1 = q1n; q2 = q2n;
        }
    }
    // exclusive shift (identity into lane 0)
    float pe  = __shfl_up_sync(FULLMASK, p,  1);
    float re  = __shfl_up_sync(FULLMASK, r,  1);
    float q1e = __shfl_up_sync(FULLMASK, q1, 1);
    float q2e = __shfl_up_sync(FULLMASK, q2, 1);
    if (lane == 0) { pe = 1.f; re = 0.f; q1e = 0.f; q2e = 0.f; }

    float y1i = fmaf(pe, y0, q1e);
    float y2i = fmaf(re + pe, y0, q2e);
    float contrib = fmaf(a1, y1i, fmaf(a2, y2i, bt));

    #pragma unroll
    for (int d = 16; d; d >>= 1) {
        contrib += __shfl_xor_sync(FULLMASK, contrib, d);
        ws      += __shfl_xor_sync(FULLMASK, ws, d);
    }
    if (lane == 0) out[row] = contrib / ws;
}

extern "C" void kernel_launch(void* const* d_in, const int* in_sizes, int n_in,
                              void* d_out, int out_size) {
    const float* X        = (const float*)d_in[0];
    const float* features = (const float*)d_in[1];
    const float* F        = (const float*)d_in[2];
    const float* bn0_g    = (const float*)d_in[3];
    const float* bn0_b    = (const float*)d_in[4];
    const float* W1       = (const float*)d_in[5];
    const float* b1       = (const float*)d_in[6];
    const float* bn1_g    = (const float*)d_in[7];
    const float* bn1_b    = (const float*)d_in[8];
    const float* W2       = (const float*)d_in[9];
    const float* b2       = (const float*)d_in[10];
    const float* bn2_g    = (const float*)d_in[11];
    const float* bn2_b    = (const float*)d_in[12];
    const float* W3       = (const float*)d_in[13];
    const float* b3       = (const float*)d_in[14];
    const float* pn       = (const float*)d_in[15];
    float* out = (float*)d_out;

    k1_stats0<<<8, 256>>>(features);
    k2_h1<<<16, 128>>>(features, bn0_g, bn0_b, W1, b1);
    k3_h2<<<16, 128>>>(bn1_g, bn1_b, W2, b2);
    k4_params<<<16, 128>>>(bn2_g, bn2_b, W3, b3, pn);
    k5_scan<<<256, 256>>>(X, F, out);
}